// round 15
// baseline (speedup 1.0000x reference)
#include <cuda_runtime.h>

// PatchExtractor3d: out[b, c*27 + i*9 + j*3 + l, d, h, w] = xpad[b, c, d+i, h+j, w+l]
// x [2,3,32,128,128] fp32 -> out [2,81,32,128,128] fp32, pad=1, K=3.
//
// R6 gather structure (block = one (b,co,d) plane; cross-warp instantaneous
// contiguity: at step it the 8 warps cover 16 contiguous rows) upgraded to
// 256-bit LDG/STG (sm_100a v8.f32). Lane = 8 floats; warp access = 2 rows.

static constexpr int B_  = 2;
static constexpr int C_  = 3;
static constexpr int D_  = 32;
static constexpr int H_  = 128;
static constexpr int W_  = 128;
static constexpr int COUT = C_ * 27;   // 81

struct F8 { float f[8]; };

__device__ __forceinline__ F8 ldg256(const float* p) {
    F8 v;
    asm volatile("ld.global.nc.v8.f32 {%0,%1,%2,%3,%4,%5,%6,%7}, [%8];"
        : "=f"(v.f[0]), "=f"(v.f[1]), "=f"(v.f[2]), "=f"(v.f[3]),
          "=f"(v.f[4]), "=f"(v.f[5]), "=f"(v.f[6]), "=f"(v.f[7])
        : "l"(p));
    return v;
}
__device__ __forceinline__ void stg256(float* p, const F8& v) {
    asm volatile("st.global.cs.v8.f32 [%0], {%1,%2,%3,%4,%5,%6,%7,%8};"
        :: "l"(p),
           "f"(v.f[0]), "f"(v.f[1]), "f"(v.f[2]), "f"(v.f[3]),
           "f"(v.f[4]), "f"(v.f[5]), "f"(v.f[6]), "f"(v.f[7])
        : "memory");
}

template<int L>
__device__ __forceinline__ F8 shift_row(const F8& v, int lane) {
    if (L == 1) return v;
    F8 r;
    if (L == 0) {                        // out[w] = in[w-1]
        const float pv = __shfl_up_sync(0xffffffffu, v.f[7], 1);
        r.f[0] = ((lane & 15) == 0) ? 0.f : pv;   // row boundary at 16-lane edge
        #pragma unroll
        for (int k = 1; k < 8; ++k) r.f[k] = v.f[k - 1];
    } else {                             // out[w] = in[w+1]
        const float nv = __shfl_down_sync(0xffffffffu, v.f[0], 1);
        #pragma unroll
        for (int k = 0; k < 7; ++k) r.f[k] = v.f[k + 1];
        r.f[7] = ((lane & 15) == 15) ? 0.f : nv;
    }
    return r;
}

template<int L>
__device__ __forceinline__ void do_plane(const float* __restrict__ xplane,
                                         float* __restrict__ obase /* plane, float addr */,
                                         int warp, int lane, int j) {
    const int sub  = lane >> 4;          // 0/1: which of the 2 rows
    const int c8   = (lane & 15) * 8;    // float offset within row
    F8 v[8];
    // Phase 1: 8 front-batched 256-bit loads (warp covers rows 2*(warp+8it)+sub)
    #pragma unroll
    for (int it = 0; it < 8; ++it) {
        const int hin = 2 * (warp + it * 8) + sub + j - 1;
        if ((unsigned)hin < (unsigned)H_)
            v[it] = ldg256(xplane + (size_t)hin * W_ + c8);
        else
            #pragma unroll
            for (int k = 0; k < 8; ++k) v[it].f[k] = 0.f;
    }
    // Phase 2: shift + 256-bit streaming stores (2-row chunk contiguous)
    #pragma unroll
    for (int it = 0; it < 8; ++it) {
        const int r0 = 2 * (warp + it * 8);
        stg256(obase + (size_t)r0 * W_ + lane * 8, shift_row<L>(v[it], lane));
    }
}

__global__ __launch_bounds__(256, 3)
void patch3d_kernel(const float* __restrict__ x, float* __restrict__ out) {
    const int d    = blockIdx.x;       // 0..31
    const int co   = blockIdx.y;       // 0..80
    const int b    = blockIdx.z;       // 0..1
    const int warp = threadIdx.x >> 5;
    const int lane = threadIdx.x & 31;

    // Block-uniform decomposition
    const int c   = co / 27;
    const int rem = co - c * 27;
    const int i   = rem / 9;
    const int jl  = rem - i * 9;
    const int j   = jl / 3;
    const int l   = jl - j * 3;
    const int din = d + i - 1;

    float* const obase = out + ((size_t)((b * COUT + co) * D_ + d) * H_) * W_;

    if ((unsigned)din >= (unsigned)D_) {
        // whole plane is padding -> 256-bit zero-store stream
        F8 z;
        #pragma unroll
        for (int k = 0; k < 8; ++k) z.f[k] = 0.f;
        #pragma unroll
        for (int it = 0; it < 8; ++it) {
            const int r0 = 2 * (warp + it * 8);
            stg256(obase + (size_t)r0 * W_ + lane * 8, z);
        }
        return;
    }

    const float* xplane = x + (((size_t)(b * C_ + c) * D_ + din) * H_) * W_;

    if (l == 0)      do_plane<0>(xplane, obase, warp, lane, j);
    else if (l == 1) do_plane<1>(xplane, obase, warp, lane, j);
    else             do_plane<2>(xplane, obase, warp, lane, j);
}

extern "C" void kernel_launch(void* const* d_in, const int* in_sizes, int n_in,
                              void* d_out, int out_size) {
    const float* x = (const float*)d_in[0];
    float* out = (float*)d_out;
    (void)in_sizes; (void)n_in; (void)out_size;

    dim3 grid(D_, COUT, B_);           // (32, 81, 2) = 5184 blocks
    patch3d_kernel<<<grid, 256>>>(x, out);
}

// round 17
// speedup vs baseline: 1.0330x; 1.0330x over previous
#include <cuda_runtime.h>

// PatchExtractor3d: out[b, c*27 + i*9 + j*3 + l, d, h, w] = xpad[b, c, d+i, h+j, w+l]
// x [2,3,32,128,128] fp32 -> out [2,81,32,128,128] fp32, pad=1, K=3.
//
// FINAL (champion, R6): block = one (b, co, d) output plane; index math
// block-uniform. Warp owns rows h = warp + it*8 -> at each unrolled step the
// 8 warps of the block store 8 contiguous rows (dense 4KB cross-warp burst).
// 16 front-batched LDG.128 per warp (MLP=16), then 16 shfl + STG.128 (__stcs).
// Measured at the HBM write-stream ceiling (~6.6 TB/s effective).

static constexpr int B_  = 2;
static constexpr int C_  = 3;
static constexpr int D_  = 32;
static constexpr int H_  = 128;
static constexpr int W_  = 128;
static constexpr int COUT = C_ * 27;   // 81

template<int L>
__device__ __forceinline__ float4 shift_row(float4 cur, int lane) {
    if (L == 1) return cur;
    float4 r;
    if (L == 0) {                       // out[w] = in[w-1]
        const float pw = __shfl_up_sync(0xffffffffu, cur.w, 1);
        r.x = (lane == 0) ? 0.f : pw;
        r.y = cur.x; r.z = cur.y; r.w = cur.z;
    } else {                            // out[w] = in[w+1]
        const float nx = __shfl_down_sync(0xffffffffu, cur.x, 1);
        r.x = cur.y; r.y = cur.z; r.z = cur.w;
        r.w = (lane == 31) ? 0.f : nx;
    }
    return r;
}

template<int L>
__device__ __forceinline__ void do_plane(const float* __restrict__ xplane,
                                         float4* __restrict__ o4,
                                         int warp, int lane, int j) {
    // warp handles rows h = warp + it*8, it = 0..15
    float4 v[16];
    // Phase 1: 16 front-batched independent loads (max MLP)
    #pragma unroll
    for (int k = 0; k < 16; ++k) {
        const int h   = warp + k * 8;
        const int hin = h + j - 1;
        if ((unsigned)hin < (unsigned)H_) {
            const float4* p =
                reinterpret_cast<const float4*>(xplane + (size_t)hin * W_) + lane;
            v[k] = __ldg(p);
        } else {
            v[k] = make_float4(0.f, 0.f, 0.f, 0.f);
        }
    }
    // Phase 2: shift + streaming stores
    #pragma unroll
    for (int k = 0; k < 16; ++k) {
        const int h = warp + k * 8;
        __stcs(o4 + (size_t)h * (W_ / 4), shift_row<L>(v[k], lane));
    }
}

__global__ __launch_bounds__(256, 3)
void patch3d_kernel(const float* __restrict__ x, float* __restrict__ out) {
    const int d    = blockIdx.x;       // 0..31
    const int co   = blockIdx.y;       // 0..80
    const int b    = blockIdx.z;       // 0..1
    const int warp = threadIdx.x >> 5;
    const int lane = threadIdx.x & 31;

    // Block-uniform decomposition
    const int c   = co / 27;
    const int rem = co - c * 27;
    const int i   = rem / 9;
    const int jl  = rem - i * 9;
    const int j   = jl / 3;
    const int l   = jl - j * 3;
    const int din = d + i - 1;

    float4* o4 = reinterpret_cast<float4*>(out)
               + ((size_t)((b * COUT + co) * D_ + d) * H_) * (W_ / 4) + lane;

    if ((unsigned)din >= (unsigned)D_) {
        // whole plane is padding -> pure zero-store loop
        const float4 z = make_float4(0.f, 0.f, 0.f, 0.f);
        #pragma unroll
        for (int it = 0; it < 16; ++it)
            __stcs(o4 + (size_t)(warp + it * 8) * (W_ / 4), z);
        return;
    }

    const float* xplane = x + (((size_t)(b * C_ + c) * D_ + din) * H_) * W_;

    if (l == 0)      do_plane<0>(xplane, o4, warp, lane, j);
    else if (l == 1) do_plane<1>(xplane, o4, warp, lane, j);
    else             do_plane<2>(xplane, o4, warp, lane, j);
}

extern "C" void kernel_launch(void* const* d_in, const int* in_sizes, int n_in,
                              void* d_out, int out_size) {
    const float* x = (const float*)d_in[0];
    float* out = (float*)d_out;
    (void)in_sizes; (void)n_in; (void)out_size;

    dim3 grid(D_, COUT, B_);           // (32, 81, 2) = 5184 blocks
    patch3d_kernel<<<grid, 256>>>(x, out);
}